// round 5
// baseline (speedup 1.0000x reference)
#include <cuda_runtime.h>

#define BATCH 131072
#define NCH 16
#define NK 15
#define NZ 256
#define NCOUT 10
#define MAXREG 128
#define VOCAB 1024

typedef unsigned long long u64;

// ---------------- scratch (device globals; no allocation) ----------------
__device__ unsigned       g_seen[NCH][1024];     // built by k_masks, read by k_pair, zeroed by k_resolve
__device__ unsigned       g_bits[NCH][1024];     // bits snapshot for rank queries
__device__ unsigned char  g_pref[NCH][1024];     // per-word exclusive popcount prefix
__device__ unsigned       g_maskw[BATCH * 8];    // packed masks: channel pair per u32
__device__ unsigned char  g_cross[8][MAXREG][MAXREG];  // argmax index per (c8, rA, rB)
__device__ u64            g_idx8[BATCH];         // packed 8 cross indices per element

// ================= K1: per-element sign masks (f32x2 packed planes) =================
#define K1_BLK 296
#define K1_THR 512
#define K1_SMEM (8192 + 8192 + 2880 + 65536)   // 84800 B

__global__ void __launch_bounds__(K1_THR, 2) k_masks(
    const int* __restrict__ x, const float* __restrict__ lenLUT,
    const float* __restrict__ ipdLUT, const float* __restrict__ S,
    const float* __restrict__ T)
{
    extern __shared__ char dyn[];
    float2*   sLen = (float2*)dyn;                       // 8 KB
    float2*   sIpd = (float2*)(dyn + 8192);              // 8 KB
    u64*      sS0  = (u64*)(dyn + 16384);                // 8 pairs x 15 k, packed (cA,cB)
    u64*      sS1  = sS0 + 120;
    u64*      sC   = sS1 + 120;                          // packed (-T-1e-4)
    unsigned* filt = (unsigned*)(dyn + 16384 + 2880);    // 64 KB block-local seen filter

    const int tid = threadIdx.x;
    for (int i = tid; i < VOCAB; i += K1_THR) {
        sLen[i] = ((const float2*)lenLUT)[i];
        sIpd[i] = ((const float2*)ipdLUT)[i];
    }
    if (tid < 120) {                                     // pack per-pair plane constants
        int i = tid / NK, k = tid % NK;
        int cA = 2 * i, cB = 2 * i + 1;
        u64 s0 = ((u64)__float_as_uint(S[cB * 30 + k])      << 32) | __float_as_uint(S[cA * 30 + k]);
        u64 s1 = ((u64)__float_as_uint(S[cB * 30 + 15 + k]) << 32) | __float_as_uint(S[cA * 30 + 15 + k]);
        float cAv = -T[cA * NK + k] - 1e-4f;
        float cBv = -T[cB * NK + k] - 1e-4f;
        u64 cc = ((u64)__float_as_uint(cBv) << 32) | __float_as_uint(cAv);
        sS0[tid] = s0; sS1[tid] = s1; sC[tid] = cc;
    }
    for (int i = tid; i < NCH * 1024; i += K1_THR) filt[i] = 0u;
    __syncthreads();

    const int b = blockIdx.x * K1_THR + tid;
    if (b >= BATCH) return;
    const int4* xp = (const int4*)x + (size_t)b * 8;
    int4 xq[8];
    #pragma unroll
    for (int i = 0; i < 8; i++) xq[i] = xp[i];           // 8x LDG.128, all in flight

    unsigned words[8];
    #pragma unroll
    for (int i = 0; i < 8; i++) {
        int4   xv = xq[i];
        float2 lA = sLen[xv.x], pA = sIpd[xv.y];
        float2 lB = sLen[xv.z], pB = sIpd[xv.w];
        float e0A = lA.x + pA.x, e1A = lA.y + pA.y;
        float e0B = lB.x + pB.x, e1B = lB.y + pB.y;
        u64 e0p, e1p;
        asm("mov.b64 %0, {%1, %2};" : "=l"(e0p) : "f"(e0A), "f"(e0B));
        asm("mov.b64 %0, {%1, %2};" : "=l"(e1p) : "f"(e1A), "f"(e1B));
        unsigned pair = 0;
        #pragma unroll
        for (int k = 0; k < NK; k++) {
            u64 t2, y2;
            asm("fma.rn.f32x2 %0, %1, %2, %3;" : "=l"(t2) : "l"(e0p), "l"(sS0[i * NK + k]), "l"(sC[i * NK + k]));
            asm("fma.rn.f32x2 %0, %1, %2, %3;" : "=l"(y2) : "l"(e1p), "l"(sS1[i * NK + k]), "l"(t2));
            unsigned lo = (unsigned)y2;
            unsigned hi = (unsigned)(y2 >> 32);
            pair |= ((lo >> 31) << k) | ((hi >> 31) << (16 + k));   // bit set <=> y<0
        }
        words[i] = pair;
        #pragma unroll
        for (int h = 0; h < 2; h++) {
            unsigned m = (pair >> (16 * h)) & 0xffffu;
            int c = 2 * i + h;
            unsigned word = c * 1024 + (m >> 5), bit = 1u << (m & 31);
            if (!(filt[word] & bit)) {                   // cheap smem pre-filter
                unsigned old = atomicOr(&filt[word], bit);
                if (!(old & bit)) atomicOr(&g_seen[c][m >> 5], bit);
            }
        }
    }
    uint4* mp = (uint4*)&g_maskw[(size_t)b * 8];
    mp[0] = make_uint4(words[0], words[1], words[2], words[3]);
    mp[1] = make_uint4(words[4], words[5], words[6], words[7]);
}

// ================= K2: per-pair dedup + smem z-rows + cross argmax =================
#define K2_SH_H  0
#define K2_SH_ZA 30720
#define K2_SH_ZB 63488
#define K2_SMEM  (63488 + 131072)   // 194560 B

__global__ void __launch_bounds__(1024) k_pair(const float* __restrict__ H) {
    const int q = blockIdx.x, c8 = blockIdx.y;
    const int cA = 2 * c8, cB = cA + 1;
    const int tid = threadIdx.x;
    extern __shared__ char dyn[];
    float (*sH)[NZ]  = (float(*)[NZ])(dyn + K2_SH_H);    // 30 x 256
    float (*zA)[NZ]  = (float(*)[NZ])(dyn + K2_SH_ZA);   // 32 x 256
    float (*zBr)[NZ] = (float(*)[NZ])(dyn + K2_SH_ZB);   // 128 x 256
    __shared__ int            scn[2][256];
    __shared__ unsigned short sMaskA[MAXREG], sMaskB[MAXREG];
    __shared__ int            sNA, sNB;

    for (int i = tid; i < 30 * NZ; i += 1024) sH[i >> 8][i & 255] = H[i];

    // dedup both channels: threads 0..255 -> cA, 256..511 -> cB
    const int half = tid >> 8;
    const int lt   = tid & 255;
    unsigned w[4]; int pc = 0;
    if (tid < 512) {
        int c = half ? cB : cA;
        #pragma unroll
        for (int j = 0; j < 4; j++) { w[j] = g_seen[c][lt * 4 + j]; pc += __popc(w[j]); }
        scn[half][lt] = pc;
    }
    __syncthreads();
    for (int off = 1; off < 256; off <<= 1) {            // two 256-lane inclusive scans
        int v = 0;
        if (tid < 512 && lt >= off) v = scn[half][lt - off];
        __syncthreads();
        if (tid < 512) scn[half][lt] += v;
        __syncthreads();
    }
    if (tid < 512) {
        int id = scn[half][lt] - pc;                     // exclusive prefix (ascending-mask order)
        if (lt == 255) { if (half) sNB = min(scn[1][255], MAXREG); else sNA = min(scn[0][255], MAXREG); }
        int c = half ? cB : cA;
        unsigned short* sM = half ? sMaskB : sMaskA;
        #pragma unroll
        for (int j = 0; j < 4; j++) {
            const int word = lt * 4 + j;
            if (q == 0) { g_bits[c][word] = w[j]; g_pref[c][word] = (unsigned char)id; }
            unsigned ww = w[j];
            const unsigned mb = (unsigned)word << 5;
            while (ww) {
                int bb = __ffs(ww) - 1; ww &= ww - 1;
                if (id < MAXREG) sM[id] = (unsigned short)(mb | (unsigned)bb);
                id++;
            }
        }
    }
    __syncthreads();

    const int nA = sNA, nB = sNB;
    const int rA0 = q * 32;
    const int na  = min(32, max(0, nA - rA0));
    const int col = tid & 255, grp = tid >> 8;

    for (int r = grp; r < nB; r += 4) {                  // full B z-rows (cB -> H rows 15..29)
        unsigned m = sMaskB[r];
        float acc = 0.f;
        #pragma unroll
        for (int d = 0; d < NK; d++) { float hv = sH[15 + d][col]; acc += ((m >> d) & 1) ? -hv : hv; }
        zBr[r][col] = acc;
    }
    for (int r = grp; r < na; r += 4) {                  // quarter of A z-rows (cA -> H rows 0..14)
        unsigned m = sMaskA[rA0 + r];
        float acc = 0.f;
        #pragma unroll
        for (int d = 0; d < NK; d++) { float hv = sH[d][col]; acc += ((m >> d) & 1) ? -hv : hv; }
        zA[r][col] = acc;
    }
    __syncthreads();
    if (na <= 0) return;                                 // uniform across block

    const int warp = tid >> 5, lane = tid & 31;
    for (int rAl = 0; rAl < na; rAl++) {
        float za[8];
        #pragma unroll
        for (int j = 0; j < 8; j++) za[j] = zA[rAl][j * 32 + lane];
        for (int rB = warp; rB < nB; rB += 32) {
            float best = __int_as_float(0xff800000);     // -inf
            int   bk = 0;
            #pragma unroll
            for (int j = 0; j < 8; j++) {
                int k = j * 32 + lane;                   // ascending per lane
                float v = za[j] + zBr[rB][k];
                if (v > best) { best = v; bk = k; }
            }
            #pragma unroll
            for (int off = 16; off; off >>= 1) {         // first-index-wins warp argmax
                float ov = __shfl_down_sync(0xffffffffu, best, off);
                int   ok = __shfl_down_sync(0xffffffffu, bk, off);
                if (ov > best || (ov == best && ok < bk)) { best = ov; bk = ok; }
            }
            if (lane == 0) g_cross[c8][rA0 + rAl][rB] = (unsigned char)bk;
        }
    }
}

// ================= K3: masks -> packed cross indices (all gathers in smem) =================
#define KR_SMEM (65536 + 16384 + 131072)   // 212992 B

__global__ void __launch_bounds__(1024, 1) k_resolve() {
    extern __shared__ char dyn[];
    unsigned*      sbits  = (unsigned*)dyn;                    // 64 KB
    unsigned char* spref  = (unsigned char*)(dyn + 65536);     // 16 KB
    unsigned char* scross = (unsigned char*)(dyn + 81920);     // 128 KB

    const int tid = threadIdx.x;
    for (int i = tid; i < NCH * 1024; i += 1024) {
        sbits[i] = ((const unsigned*)g_bits)[i];
        spref[i] = ((const unsigned char*)g_pref)[i];
    }
    for (int i = tid; i < (8 * MAXREG * MAXREG) / 16; i += 1024)
        ((uint4*)scross)[i] = ((const uint4*)g_cross)[i];
    if (blockIdx.x < NCH) g_seen[blockIdx.x][tid] = 0u;   // self-clean for next launch
    __syncthreads();

    const int b = blockIdx.x * 1024 + tid;
    if (b >= BATCH) return;
    const uint4* mp = (const uint4*)&g_maskw[(size_t)b * 8];
    uint4 m0 = mp[0], m1 = mp[1];
    unsigned mw[8] = {m0.x, m0.y, m0.z, m0.w, m1.x, m1.y, m1.z, m1.w};

    int r[NCH];
    #pragma unroll
    for (int i = 0; i < 8; i++) {
        #pragma unroll
        for (int h = 0; h < 2; h++) {
            unsigned m = (mw[i] >> (16 * h)) & 0xffffu;
            int c = 2 * i + h;
            unsigned word = c * 1024 + (m >> 5);
            r[c] = (int)spref[word] + __popc(sbits[word] & ((1u << (m & 31)) - 1u));
        }
    }
    u64 pack = 0;
    #pragma unroll
    for (int c8 = 0; c8 < 8; c8++) {
        unsigned idx = scross[(c8 * MAXREG + r[2 * c8]) * MAXREG + r[2 * c8 + 1]];
        pack |= (u64)idx << (8 * c8);
    }
    g_idx8[b] = pack;
}

// ================= K4: packed indices -> LUT sums + log_softmax =================
#define LUTPAD 12
#define KE_SMEM (8 * 256 * LUTPAD * 4)   // 98304 B

__global__ void __launch_bounds__(1024, 1) k_emit(
    const float* __restrict__ LUT, float* __restrict__ out)
{
    extern __shared__ char dyn[];
    float* slut = (float*)dyn;

    const int tid = threadIdx.x;
    for (int row = tid; row < 8 * 256; row += 1024) {
        #pragma unroll
        for (int j = 0; j < LUTPAD; j++)
            slut[row * LUTPAD + j] = (j < NCOUT) ? LUT[row * NCOUT + j] : 0.f;
    }
    __syncthreads();

    const int b = blockIdx.x * 1024 + tid;
    if (b >= BATCH) return;
    u64 pack = g_idx8[b];

    float4 a0 = make_float4(0.f, 0.f, 0.f, 0.f), a1 = a0, a2 = a0;
    #pragma unroll
    for (int c8 = 0; c8 < 8; c8++) {
        int idx = (int)((pack >> (8 * c8)) & 255u);
        const float4* p = (const float4*)&slut[(c8 * 256 + idx) * LUTPAD];
        float4 v0 = p[0], v1 = p[1], v2 = p[2];
        a0.x += v0.x; a0.y += v0.y; a0.z += v0.z; a0.w += v0.w;
        a1.x += v1.x; a1.y += v1.y; a1.z += v1.z; a1.w += v1.w;
        a2.x += v2.x; a2.y += v2.y;                  // lanes 10,11 are pad
    }
    float acc[NCOUT] = {a0.x, a0.y, a0.z, a0.w, a1.x, a1.y, a1.z, a1.w, a2.x, a2.y};

    float mx = acc[0];
    #pragma unroll
    for (int j = 1; j < NCOUT; j++) mx = fmaxf(mx, acc[j]);
    float s = 0.f;
    #pragma unroll
    for (int j = 0; j < NCOUT; j++) s += __expf(acc[j] - mx);
    float lg = __logf(s);

    float2* op = (float2*)(out + (size_t)b * NCOUT);
    #pragma unroll
    for (int j = 0; j < 5; j++)
        op[j] = make_float2((acc[2 * j] - mx) - lg, (acc[2 * j + 1] - mx) - lg);
}

// ---------------- launch ----------------
extern "C" void kernel_launch(void* const* d_in, const int* in_sizes, int n_in,
                              void* d_out, int out_size) {
    const int*   x      = (const int*)d_in[0];
    const float* lenLUT = (const float*)d_in[1];
    const float* ipdLUT = (const float*)d_in[2];
    const float* S      = (const float*)d_in[3];
    const float* H      = (const float*)d_in[4];
    const float* T      = (const float*)d_in[5];
    const float* LUT    = (const float*)d_in[6];
    float*       out    = (float*)d_out;

    static int attr_done = 0;   // host-side, idempotent (set on the pre-capture correctness call)
    if (!attr_done) {
        cudaFuncSetAttribute(k_masks,   cudaFuncAttributeMaxDynamicSharedMemorySize, K1_SMEM);
        cudaFuncSetAttribute(k_pair,    cudaFuncAttributeMaxDynamicSharedMemorySize, K2_SMEM);
        cudaFuncSetAttribute(k_resolve, cudaFuncAttributeMaxDynamicSharedMemorySize, KR_SMEM);
        cudaFuncSetAttribute(k_emit,    cudaFuncAttributeMaxDynamicSharedMemorySize, KE_SMEM);
        attr_done = 1;
    }

    k_masks  <<<K1_BLK, K1_THR, K1_SMEM>>>(x, lenLUT, ipdLUT, S, T);
    k_pair   <<<dim3(4, 8), 1024, K2_SMEM>>>(H);
    k_resolve<<<148, 1024, KR_SMEM>>>();
    k_emit   <<<148, 1024, KE_SMEM>>>(LUT, out);
}

// round 6
// speedup vs baseline: 1.7988x; 1.7988x over previous
#include <cuda_runtime.h>

#define BATCH 131072
#define NCH 16
#define NK 15
#define NZ 256
#define NCOUT 10
#define MAXREG 128
#define VOCAB 1024

typedef unsigned long long u64;

// ---------------- scratch (device globals; no allocation) ----------------
__device__ unsigned       g_seen[NCH][1024];     // built by k_masks, read+zeroed by k_tables
__device__ unsigned char  g_rmap[NCH][32768];    // mask -> region id (observed entries valid this launch)
__device__ unsigned       g_maskw[BATCH * 8];    // packed masks: channel pair per u32
__device__ int            g_cnt[NCH];            // #distinct masks per channel (<=121)
__device__ float          g_zreg[NCH][MAXREG][NZ];       // per-region half z-row
__device__ unsigned char  g_cross[8][MAXREG][MAXREG];    // argmax index per (c8, rA, rB)

// ================= K1: per-element sign masks (f32x2 packed planes) =================
#define K1_BLK 256
#define K1_THR 512
#define K1_SMEM (8192 + 8192 + 2880 + 65536)   // 84800 B

__global__ void __launch_bounds__(K1_THR, 2) k_masks(
    const int* __restrict__ x, const float* __restrict__ lenLUT,
    const float* __restrict__ ipdLUT, const float* __restrict__ S,
    const float* __restrict__ T)
{
    extern __shared__ char dyn[];
    float2*   sLen = (float2*)dyn;                       // 8 KB
    float2*   sIpd = (float2*)(dyn + 8192);              // 8 KB
    u64*      sS0  = (u64*)(dyn + 16384);                // 8 pairs x 15 k, packed (cA,cB)
    u64*      sS1  = sS0 + 120;
    u64*      sC   = sS1 + 120;                          // packed (-T-1e-4)
    unsigned* filt = (unsigned*)(dyn + 16384 + 2880);    // 64 KB block-local seen filter

    const int tid = threadIdx.x;
    for (int i = tid; i < VOCAB; i += K1_THR) {
        sLen[i] = ((const float2*)lenLUT)[i];
        sIpd[i] = ((const float2*)ipdLUT)[i];
    }
    if (tid < 120) {                                     // pack per-pair plane constants
        int i = tid / NK, k = tid % NK;
        int cA = 2 * i, cB = 2 * i + 1;
        u64 s0 = ((u64)__float_as_uint(S[cB * 30 + k])      << 32) | __float_as_uint(S[cA * 30 + k]);
        u64 s1 = ((u64)__float_as_uint(S[cB * 30 + 15 + k]) << 32) | __float_as_uint(S[cA * 30 + 15 + k]);
        float cAv = -T[cA * NK + k] - 1e-4f;
        float cBv = -T[cB * NK + k] - 1e-4f;
        u64 cc = ((u64)__float_as_uint(cBv) << 32) | __float_as_uint(cAv);
        sS0[tid] = s0; sS1[tid] = s1; sC[tid] = cc;
    }
    for (int i = tid; i < NCH * 1024; i += K1_THR) filt[i] = 0u;
    __syncthreads();

    const int b = blockIdx.x * K1_THR + tid;             // exact cover: 256*512 = BATCH
    const int4* xp = (const int4*)x + (size_t)b * 8;

    unsigned words[8];
    #pragma unroll
    for (int i = 0; i < 8; i++) {
        int4   xv = __ldg(&xp[i]);                       // short live range: no bulk staging
        float2 lA = sLen[xv.x], pA = sIpd[xv.y];
        float2 lB = sLen[xv.z], pB = sIpd[xv.w];
        float e0A = lA.x + pA.x, e1A = lA.y + pA.y;
        float e0B = lB.x + pB.x, e1B = lB.y + pB.y;
        u64 e0p, e1p;
        asm("mov.b64 %0, {%1, %2};" : "=l"(e0p) : "f"(e0A), "f"(e0B));
        asm("mov.b64 %0, {%1, %2};" : "=l"(e1p) : "f"(e1A), "f"(e1B));
        unsigned pair = 0;
        #pragma unroll
        for (int k = 0; k < NK; k++) {
            u64 t2, y2;
            asm("fma.rn.f32x2 %0, %1, %2, %3;" : "=l"(t2) : "l"(e0p), "l"(sS0[i * NK + k]), "l"(sC[i * NK + k]));
            asm("fma.rn.f32x2 %0, %1, %2, %3;" : "=l"(y2) : "l"(e1p), "l"(sS1[i * NK + k]), "l"(t2));
            unsigned lo = (unsigned)y2;
            unsigned hi = (unsigned)(y2 >> 32);
            pair |= ((lo >> 31) << k) | ((hi >> 31) << (16 + k));   // bit set <=> y<0
        }
        words[i] = pair;
    }

    uint4* mp = (uint4*)&g_maskw[(size_t)b * 8];
    mp[0] = make_uint4(words[0], words[1], words[2], words[3]);
    mp[1] = make_uint4(words[4], words[5], words[6], words[7]);

    // seen-set update pass (block filter -> rare global atomic)
    #pragma unroll
    for (int i = 0; i < 8; i++) {
        #pragma unroll
        for (int h = 0; h < 2; h++) {
            unsigned m = (words[i] >> (16 * h)) & 0xffffu;
            int c = 2 * i + h;
            unsigned word = c * 1024 + (m >> 5), bit = 1u << (m & 31);
            if (!(filt[word] & bit)) {
                unsigned old = atomicOr(&filt[word], bit);
                if (!(old & bit)) atomicOr(&g_seen[c][m >> 5], bit);
            }
        }
    }
}

// ================= K2: dedup + global region map + self-clean + zreg =================
__global__ void __launch_bounds__(1024) k_tables(const float* __restrict__ H) {  // <<<16, 1024>>>
    const int c = blockIdx.x, tid = threadIdx.x;
    __shared__ int            sc[256];
    __shared__ unsigned short sMask[MAXREG];
    __shared__ float          sH[NK][NZ];
    __shared__ int            s_cnt;

    unsigned w[4]; int pc = 0;
    if (tid < 256) {
        #pragma unroll
        for (int j = 0; j < 4; j++) {
            w[j] = g_seen[c][tid * 4 + j];
            g_seen[c][tid * 4 + j] = 0u;               // self-clean for next launch
            pc += __popc(w[j]);
        }
        sc[tid] = pc;
    }
    const int base = (c & 1) * NK;                     // even ch -> H rows 0..14, odd -> 15..29
    for (int i = tid; i < NK * NZ; i += 1024)
        sH[i >> 8][i & 255] = H[(base + (i >> 8)) * NZ + (i & 255)];
    __syncthreads();
    for (int off = 1; off < 256; off <<= 1) {          // Hillis-Steele inclusive scan (256 lanes)
        int v = 0;
        if (tid < 256 && tid >= off) v = sc[tid - off];
        __syncthreads();
        if (tid < 256) sc[tid] += v;
        __syncthreads();
    }
    if (tid < 256) {
        int id = sc[tid] - pc;                         // exclusive prefix (ascending-mask order)
        if (tid == 255) { g_cnt[c] = min(sc[255], MAXREG); s_cnt = min(sc[255], MAXREG); }
        #pragma unroll
        for (int j = 0; j < 4; j++) {
            const int word = tid * 4 + j;
            unsigned ww = w[j];
            const unsigned mb = (unsigned)word << 5;
            while (ww) {
                int bb = __ffs(ww) - 1; ww &= ww - 1;
                if (id < MAXREG) {
                    unsigned short mask = (unsigned short)(mb | (unsigned)bb);
                    g_rmap[c][mask] = (unsigned char)id;   // global mask -> region id
                    sMask[id] = mask;
                }
                id++;
            }
        }
    }
    __syncthreads();

    const int cnt = s_cnt;
    const int col = tid & 255, grp = tid >> 8;         // 4-way row parallelism
    for (int r = grp; r < cnt; r += 4) {
        unsigned m = sMask[r];
        float acc = 0.f;
        #pragma unroll
        for (int d = 0; d < NK; d++) {
            float hv = sH[d][col];
            acc += ((m >> d) & 1) ? -hv : hv;
        }
        g_zreg[c][r][col] = acc;
    }
}

// ================= K3: argmax table, rA tiled x4 =================
__global__ void k_cross() {   // <<<dim3(32, 8), 256>>>
    const int c8 = blockIdx.y, rAt = blockIdx.x;
    const int cA = 2 * c8, cB = cA + 1;
    const int nA = g_cnt[cA], nB = g_cnt[cB];
    const int rA0 = rAt * 4;
    if (rA0 >= nA) return;
    const int na = min(4, nA - rA0);
    __shared__ float zA[4][NZ];
    for (int i = threadIdx.x; i < 4 * NZ; i += 256) {
        int rr = i >> 8, k = i & 255;
        zA[rr][k] = (rr < na) ? g_zreg[cA][rA0 + rr][k] : 0.f;
    }
    __syncthreads();
    const int warp = threadIdx.x >> 5, lane = threadIdx.x & 31;
    for (int rB = warp; rB < nB; rB += 8) {
        const float* zb = &g_zreg[cB][rB][0];
        float zl[8];
        #pragma unroll
        for (int j = 0; j < 8; j++) zl[j] = zb[j * 32 + lane];
        #pragma unroll
        for (int i2 = 0; i2 < 4; i2++) {
            float best = __int_as_float(0xff800000);  // -inf
            int   bk = 0;
            #pragma unroll
            for (int j = 0; j < 8; j++) {
                int k = j * 32 + lane;                // ascending per lane
                float v = zA[i2][k] + zl[j];
                if (v > best) { best = v; bk = k; }
            }
            #pragma unroll
            for (int off = 16; off; off >>= 1) {      // first-index-wins warp argmax
                float ov = __shfl_down_sync(0xffffffffu, best, off);
                int   ok = __shfl_down_sync(0xffffffffu, bk, off);
                if (ov > best || (ov == best && ok < bk)) { best = ov; bk = ok; }
            }
            if (lane == 0 && i2 < na) g_cross[c8][rA0 + i2][rB] = (unsigned char)bk;
        }
    }
}

// ================= K4: gather (L2 rmap/cross + smem LUT) + log_softmax =================
#define K4_BLK 256
#define K4_THR 512
#define LUTPAD 12
#define K4_SMEM (8 * 256 * LUTPAD * 4)   // 98304 B -> 2 blocks/SM

__global__ void __launch_bounds__(K4_THR, 2) k_main(
    const float* __restrict__ LUT, float* __restrict__ out)
{
    extern __shared__ char dyn[];
    float* slut = (float*)dyn;

    const int tid = threadIdx.x;
    for (int row = tid; row < 8 * 256; row += K4_THR) {
        #pragma unroll
        for (int j = 0; j < LUTPAD; j++)
            slut[row * LUTPAD + j] = (j < NCOUT) ? LUT[row * NCOUT + j] : 0.f;
    }
    __syncthreads();

    const int b = blockIdx.x * K4_THR + tid;             // exact cover: 256*512 = BATCH
    const uint4* mp = (const uint4*)&g_maskw[(size_t)b * 8];
    uint4 m0 = mp[0], m1 = mp[1];
    unsigned mw[8] = {m0.x, m0.y, m0.z, m0.w, m1.x, m1.y, m1.z, m1.w};

    int r[NCH];
    #pragma unroll
    for (int i = 0; i < 8; i++) {                        // 16 independent L2 u8 loads
        r[2 * i]     = __ldg(&g_rmap[2 * i][mw[i] & 0xffffu]);
        r[2 * i + 1] = __ldg(&g_rmap[2 * i + 1][mw[i] >> 16]);
    }

    int idx[8];
    #pragma unroll
    for (int c8 = 0; c8 < 8; c8++)                       // 8 independent L2 u8 loads
        idx[c8] = __ldg(&g_cross[c8][r[2 * c8]][r[2 * c8 + 1]]);

    float4 a0 = make_float4(0.f, 0.f, 0.f, 0.f), a1 = a0, a2 = a0;
    #pragma unroll
    for (int c8 = 0; c8 < 8; c8++) {
        const float4* p = (const float4*)&slut[(c8 * 256 + idx[c8]) * LUTPAD];
        float4 v0 = p[0], v1 = p[1], v2 = p[2];
        a0.x += v0.x; a0.y += v0.y; a0.z += v0.z; a0.w += v0.w;
        a1.x += v1.x; a1.y += v1.y; a1.z += v1.z; a1.w += v1.w;
        a2.x += v2.x; a2.y += v2.y;                      // lanes 10,11 are pad
    }
    float acc[NCOUT] = {a0.x, a0.y, a0.z, a0.w, a1.x, a1.y, a1.z, a1.w, a2.x, a2.y};

    float mx = acc[0];
    #pragma unroll
    for (int j = 1; j < NCOUT; j++) mx = fmaxf(mx, acc[j]);
    float s = 0.f;
    #pragma unroll
    for (int j = 0; j < NCOUT; j++) s += __expf(acc[j] - mx);
    float lg = __logf(s);

    float2* op = (float2*)(out + (size_t)b * NCOUT);
    #pragma unroll
    for (int j = 0; j < 5; j++)
        op[j] = make_float2((acc[2 * j] - mx) - lg, (acc[2 * j + 1] - mx) - lg);
}

// ---------------- launch ----------------
extern "C" void kernel_launch(void* const* d_in, const int* in_sizes, int n_in,
                              void* d_out, int out_size) {
    const int*   x      = (const int*)d_in[0];
    const float* lenLUT = (const float*)d_in[1];
    const float* ipdLUT = (const float*)d_in[2];
    const float* S      = (const float*)d_in[3];
    const float* H      = (const float*)d_in[4];
    const float* T      = (const float*)d_in[5];
    const float* LUT    = (const float*)d_in[6];
    float*       out    = (float*)d_out;

    static int attr_done = 0;   // host-side, idempotent (set on the pre-capture correctness call)
    if (!attr_done) {
        cudaFuncSetAttribute(k_masks, cudaFuncAttributeMaxDynamicSharedMemorySize, K1_SMEM);
        cudaFuncSetAttribute(k_main,  cudaFuncAttributeMaxDynamicSharedMemorySize, K4_SMEM);
        attr_done = 1;
    }

    k_masks <<<K1_BLK, K1_THR, K1_SMEM>>>(x, lenLUT, ipdLUT, S, T);
    k_tables<<<16, 1024>>>(H);
    k_cross <<<dim3(32, 8), 256>>>();
    k_main  <<<K4_BLK, K4_THR, K4_SMEM>>>(LUT, out);
}